// round 6
// baseline (speedup 1.0000x reference)
#include <cuda_runtime.h>
#include <math.h>

#define RNK 8
#define DIM 2048
#define BSZ 8
#define SEQ 2048
#define ROWS_CHUNK 32
#define CHUNKS 2
#define ROWS_PER_BLOCK (ROWS_CHUNK * CHUNKS)   /* 64 */
#define SCALING 2.0f   /* 16 / r */

typedef unsigned long long ull;

// ---- packed f32x2 helpers (sm_100+; ptxas won't auto-fuse) ----
__device__ __forceinline__ void fma2(ull& acc, ull a, ull b) {
    asm("fma.rn.f32x2 %0, %1, %2, %0;" : "+l"(acc) : "l"(a), "l"(b));
}
__device__ __forceinline__ ull pack2(float s) {
    ull r; unsigned si = __float_as_uint(s);
    asm("mov.b64 %0, {%1, %1};" : "=l"(r) : "r"(si));
    return r;
}
__device__ __forceinline__ float2 unpack2(ull v) {
    unsigned lo, hi;
    asm("mov.b64 {%0, %1}, %2;" : "=r"(lo), "=r"(hi) : "l"(v));
    return make_float2(__uint_as_float(lo), __uint_as_float(hi));
}
__device__ __forceinline__ float dot4(float4 a, float4 b) {
    return a.x * b.x + a.y * b.y + a.z * b.z + a.w * b.w;
}

// ============================================================
// ONE kernel.  Block = (batch b, 64-row tile).
//  step 0: warp 0 computes gate[b] (LN -> 60-ReLU -> 4 -> softmax)
//  step 1: all threads build A[b] into 64 KB smem from Wa (dot4, L2-hot)
//  chunk loop (2 x 32 rows):
//    phase 1: warp-per-2-rows, xa = x_row . A[r]  (f32x2 FMAs, double2 loads)
//    phase 2: thread-per-4-cols, build B cols from Wb (coalesced), f32x2,
//             coalesced STG.128 with streaming hint
// ============================================================
extern __shared__ float As[];   // RNK*DIM floats = 64 KB

__global__ __launch_bounds__(512, 2)
void lorec_kernel(const float* __restrict__ x,
                  const float* __restrict__ ctr,
                  const float* __restrict__ gamma,
                  const float* __restrict__ beta,
                  const float* __restrict__ W1,
                  const float* __restrict__ b1,
                  const float* __restrict__ W2,
                  const float* __restrict__ b2,
                  const float* __restrict__ Wa,
                  const float* __restrict__ Wb,
                  float* __restrict__ out) {
    __shared__ ull   xa2_s[ROWS_CHUNK][RNK];   // packed (s,s) pairs
    __shared__ float z_s[32];
    __shared__ float h_s[60];
    __shared__ float4 gate_s;

    int b    = blockIdx.x >> 5;                 // / (SEQ/64 = 32)
    int row0 = (blockIdx.x & 31) * ROWS_PER_BLOCK;
    int warp = threadIdx.x >> 5;
    int lane = threadIdx.x & 31;

    // ---- step 0: gate MLP for batch b (warp 0 only) ----
    if (warp == 0) {
        float v = ctr[b * 32 + lane];
        float m = v;
        #pragma unroll
        for (int off = 16; off; off >>= 1) m += __shfl_xor_sync(0xffffffffu, m, off);
        m *= (1.0f / 32.0f);
        float d = v - m;
        float s = d * d;
        #pragma unroll
        for (int off = 16; off; off >>= 1) s += __shfl_xor_sync(0xffffffffu, s, off);
        s *= (1.0f / 32.0f);
        z_s[lane] = d * rsqrtf(s + 1e-5f) * gamma[lane] + beta[lane];
        __syncwarp();

        for (int j = lane; j < 60; j += 32) {
            float acc = b1[j];
            #pragma unroll
            for (int c = 0; c < 32; c++) acc += z_s[c] * W1[j * 32 + c];
            h_s[j] = fmaxf(acc, 0.0f);
        }
        __syncwarp();

        if (lane == 0) {
            float g[4];
            #pragma unroll
            for (int k = 0; k < 4; k++) {
                float acc = b2[k];
                for (int j = 0; j < 60; j++) acc += h_s[j] * W2[k * 60 + j];
                g[k] = acc;
            }
            float mx = fmaxf(fmaxf(g[0], g[1]), fmaxf(g[2], g[3]));
            float e0 = expf(g[0] - mx), e1 = expf(g[1] - mx);
            float e2 = expf(g[2] - mx), e3 = expf(g[3] - mx);
            float inv = 1.0f / (e0 + e1 + e2 + e3);
            gate_s = make_float4(e0 * inv, e1 * inv, e2 * inv, e3 * inv);
        }
    }
    __syncthreads();

    float4 g4 = gate_s;

    // ---- step 1: build A[b] into smem: As[r*DIM+d] = gate . Wa[r*DIM+d] ----
    {
        const float4* Wa4 = (const float4*)Wa;
        #pragma unroll
        for (int i = threadIdx.x; i < RNK * DIM; i += 512)
            As[i] = dot4(g4, __ldg(Wa4 + i));
    }
    __syncthreads();

    const double2* As2 = (const double2*)As;
    const float4*  Wb4 = (const float4*)Wb;

    #pragma unroll
    for (int c = 0; c < CHUNKS; c++) {
        int r0 = row0 + c * ROWS_CHUNK;

        // ---- phase 1: warp handles 2 rows; f32x2 dot products vs smem A ----
        {
            const double2* x0 =
                (const double2*)(x + ((size_t)b * SEQ + r0 + warp * 2) * DIM);
            const double2* x1 = x0 + (DIM / 4);     // one row = DIM/4 double2
            ull acc0[RNK], acc1[RNK];
            #pragma unroll
            for (int r = 0; r < RNK; r++) { acc0[r] = 0ull; acc1[r] = 0ull; }

            #pragma unroll 4
            for (int k = 0; k < 16; k++) {
                int d4 = k * 32 + lane;             // 16-byte chunk idx in [0,512)
                double2 xv0 = __ldcs(x0 + d4);
                double2 xv1 = __ldcs(x1 + d4);
                ull x0a = __double_as_longlong(xv0.x), x0b = __double_as_longlong(xv0.y);
                ull x1a = __double_as_longlong(xv1.x), x1b = __double_as_longlong(xv1.y);
                #pragma unroll
                for (int r = 0; r < RNK; r++) {
                    double2 a = As2[r * 512 + d4];
                    ull aa = __double_as_longlong(a.x), ab = __double_as_longlong(a.y);
                    fma2(acc0[r], x0a, aa); fma2(acc0[r], x0b, ab);
                    fma2(acc1[r], x1a, aa); fma2(acc1[r], x1b, ab);
                }
            }
            #pragma unroll
            for (int r = 0; r < RNK; r++) {
                float2 f0 = unpack2(acc0[r]);
                float2 f1 = unpack2(acc1[r]);
                float s0 = f0.x + f0.y;
                float s1 = f1.x + f1.y;
                #pragma unroll
                for (int off = 16; off; off >>= 1) {
                    s0 += __shfl_xor_sync(0xffffffffu, s0, off);
                    s1 += __shfl_xor_sync(0xffffffffu, s1, off);
                }
                if (lane == 0) {
                    xa2_s[warp * 2 + 0][r] = pack2(s0);
                    xa2_s[warp * 2 + 1][r] = pack2(s1);
                }
            }
        }
        __syncthreads();

        // ---- phase 2: build this thread's B cols from Wb, then 32 rows ----
        {
            // thread owns output cols [4*tid, 4*tid+4).  Wb row j (j=r*DIM+o)
            // is one float4 (ctr_final=4), so B col o for rank r = g4 . Wb4[r*DIM+o].
            ull Br0[RNK], Br1[RNK];
            #pragma unroll
            for (int r = 0; r < RNK; r++) {
                const float4* base = Wb4 + r * DIM + 4 * threadIdx.x;
                float4 w0 = __ldg(base + 0);
                float4 w1 = __ldg(base + 1);
                float4 w2 = __ldg(base + 2);
                float4 w3 = __ldg(base + 3);
                float4 bc = make_float4(dot4(g4, w0) * SCALING,
                                        dot4(g4, w1) * SCALING,
                                        dot4(g4, w2) * SCALING,
                                        dot4(g4, w3) * SCALING);
                ulonglong2 p = *(ulonglong2*)&bc;
                Br0[r] = p.x;
                Br1[r] = p.y;
            }

            float4* orow = (float4*)(out + ((size_t)b * SEQ + r0) * DIM) + threadIdx.x;
            #pragma unroll
            for (int i = 0; i < ROWS_CHUNK; i++) {
                ull o0 = 0ull, o1 = 0ull;
                #pragma unroll
                for (int r = 0; r < RNK; r++) {
                    ull s2 = xa2_s[i][r];           // LDS.64 broadcast
                    fma2(o0, s2, Br0[r]);
                    fma2(o1, s2, Br1[r]);
                }
                ulonglong2 ov; ov.x = o0; ov.y = o1;
                __stcs(orow, *(float4*)&ov);
                orow += DIM / 4;
            }
        }
        __syncthreads();   // protect xa2_s before next chunk
    }
}

// ============================================================
// launcher — single launch
// ============================================================
extern "C" void kernel_launch(void* const* d_in, const int* in_sizes, int n_in,
                              void* d_out, int out_size) {
    const float* x     = (const float*)d_in[0];
    const float* ctr   = (const float*)d_in[1];
    const float* gamma = (const float*)d_in[2];
    const float* beta  = (const float*)d_in[3];
    const float* W1    = (const float*)d_in[4];
    const float* b1    = (const float*)d_in[5];
    const float* W2    = (const float*)d_in[6];
    const float* b2    = (const float*)d_in[7];
    const float* Wa    = (const float*)d_in[8];
    const float* Wb    = (const float*)d_in[9];
    float* out = (float*)d_out;

    static bool attr_set = false;
    if (!attr_set) {
        cudaFuncSetAttribute(lorec_kernel,
                             cudaFuncAttributeMaxDynamicSharedMemorySize,
                             RNK * DIM * (int)sizeof(float));
        attr_set = true;
    }

    lorec_kernel<<<BSZ * (SEQ / ROWS_PER_BLOCK), 512,
                   RNK * DIM * sizeof(float)>>>(
        x, ctr, gamma, beta, W1, b1, W2, b2, Wa, Wb, out);
}

// round 7
// speedup vs baseline: 1.2491x; 1.2491x over previous
#include <cuda_runtime.h>
#include <math.h>

#define RNK 8
#define DIM 2048
#define BSZ 8
#define SEQ 2048
#define ROWS_PER_BLOCK 64
#define ROWS_PER_WARP 4
#define SCALING 2.0f   /* 16 / r */

typedef unsigned long long ull;

__device__ __forceinline__ void fma2(ull& acc, ull a, ull b) {
    asm("fma.rn.f32x2 %0, %1, %2, %0;" : "+l"(acc) : "l"(a), "l"(b));
}
__device__ __forceinline__ ull pack2(float s) {
    ull r; unsigned si = __float_as_uint(s);
    asm("mov.b64 %0, {%1, %1};" : "=l"(r) : "r"(si));
    return r;
}
__device__ __forceinline__ float dot4(float4 a, float4 b) {
    return a.x * b.x + a.y * b.y + a.z * b.z + a.w * b.w;
}

// ---- scratch ----
__device__ float g_A[BSZ * RNK * DIM];   // [b][r][d]
__device__ float g_B[BSZ * RNK * DIM];   // [b][r][o], pre-scaled by SCALING

// ============================================================
// Kernel 1: gate MLP (redundant per block, latency-overlapped with
// the Wa/Wb loads) + adapter build.  64 blocks x 512 threads.
// ============================================================
__global__ __launch_bounds__(512)
void gate_ab_kernel(const float* __restrict__ ctr,
                    const float* __restrict__ gamma,
                    const float* __restrict__ beta,
                    const float* __restrict__ W1,
                    const float* __restrict__ b1,
                    const float* __restrict__ W2,
                    const float* __restrict__ b2,
                    const float* __restrict__ Wa,
                    const float* __restrict__ Wb) {
    __shared__ float z_s[BSZ][32];
    __shared__ float h_s[BSZ][60];
    __shared__ float gate_s[BSZ][4];

    int warp = threadIdx.x >> 5;
    int lane = threadIdx.x & 31;

    // ---- hoisted: issue the big Wa/Wb load FIRST (independent of gate) ----
    int idx = blockIdx.x * 512 + threadIdx.x;          // [0, 32768)
    int j = idx & (RNK * DIM - 1);
    bool isA = idx < RNK * DIM;
    const float4* Wrow = isA ? (const float4*)Wa : (const float4*)Wb;
    float4 w4 = __ldg(Wrow + j);                        // in flight during gate

    // ---- gate MLP: warp w handles batch w ----
    if (warp < BSZ) {
        int w = warp;
        float v = ctr[w * 32 + lane];
        float m = v;
        #pragma unroll
        for (int off = 16; off; off >>= 1) m += __shfl_xor_sync(0xffffffffu, m, off);
        m *= (1.0f / 32.0f);
        float d = v - m;
        float s = d * d;
        #pragma unroll
        for (int off = 16; off; off >>= 1) s += __shfl_xor_sync(0xffffffffu, s, off);
        s *= (1.0f / 32.0f);
        z_s[w][lane] = d * rsqrtf(s + 1e-5f) * gamma[lane] + beta[lane];
        __syncwarp();

        for (int jj = lane; jj < 60; jj += 32) {
            float acc = b1[jj];
            #pragma unroll
            for (int c = 0; c < 32; c++) acc += z_s[w][c] * W1[jj * 32 + c];
            h_s[w][jj] = fmaxf(acc, 0.0f);
        }
        __syncwarp();

        if (lane == 0) {
            float g[4];
            #pragma unroll
            for (int k = 0; k < 4; k++) {
                float acc = b2[k];
                for (int jj = 0; jj < 60; jj++) acc += h_s[w][jj] * W2[k * 60 + jj];
                g[k] = acc;
            }
            float mx = fmaxf(fmaxf(g[0], g[1]), fmaxf(g[2], g[3]));
            float e0 = expf(g[0] - mx), e1 = expf(g[1] - mx);
            float e2 = expf(g[2] - mx), e3 = expf(g[3] - mx);
            float inv = 1.0f / (e0 + e1 + e2 + e3);
            gate_s[w][0] = e0 * inv;
            gate_s[w][1] = e1 * inv;
            gate_s[w][2] = e2 * inv;
            gate_s[w][3] = e3 * inv;
        }
    }
    __syncthreads();

    float* dst = isA ? g_A : g_B;
    float scale = isA ? 1.0f : SCALING;
    #pragma unroll
    for (int b = 0; b < BSZ; b++) {
        float4 g4 = *(const float4*)gate_s[b];
        dst[b * RNK * DIM + j] =
            scale * (w4.x * g4.x + w4.y * g4.y + w4.z * g4.z + w4.w * g4.w);
    }
}

// ============================================================
// Kernel 2: out[b,s,:] = (x[b,s,:] @ A[b]^T) @ B[b]   (SCALING in B)
//   256 blocks x 512 threads; block = (batch, 64-row tile).
//   A[b] staged in 64 KB smem; phase 1 = 4 rows/warp (amortizes every
//   smem A read over 4 rows -> LDS traffic halved vs 2 rows/warp);
//   single pass over all 64 rows, B built once in phase 2 (f32x2).
// ============================================================
extern __shared__ float As[];   // RNK*DIM = 64 KB

__global__ __launch_bounds__(512, 2)
void main_kernel(const float* __restrict__ x, float* __restrict__ out) {
    __shared__ ull xa2_s[ROWS_PER_BLOCK][RNK];   // packed (s,s)

    int b    = blockIdx.x >> 5;
    int row0 = (blockIdx.x & 31) * ROWS_PER_BLOCK;
    int warp = threadIdx.x >> 5;
    int lane = threadIdx.x & 31;

    // ---- stage A[b] into smem ----
    {
        const float4* src = (const float4*)(g_A + b * RNK * DIM);
        float4* dst = (float4*)As;
        #pragma unroll
        for (int i = threadIdx.x; i < (RNK * DIM) / 4; i += 512) dst[i] = src[i];
    }
    __syncthreads();

    // ---- phase 1: warp handles 4 rows; plain FFMA dot products vs smem A ----
    {
        const float4* xw =
            (const float4*)(x + ((size_t)b * SEQ + row0 + warp * ROWS_PER_WARP) * DIM);
        const float4* As4 = (const float4*)As;

        float acc[ROWS_PER_WARP][RNK];
        #pragma unroll
        for (int jr = 0; jr < ROWS_PER_WARP; jr++)
            #pragma unroll
            for (int r = 0; r < RNK; r++) acc[jr][r] = 0.0f;

        #pragma unroll 2
        for (int k = 0; k < 16; k++) {
            int d4 = k * 32 + lane;                 // float4 idx in [0,512)
            float4 xv0 = __ldcs(xw + 0 * (DIM / 4) + d4);
            float4 xv1 = __ldcs(xw + 1 * (DIM / 4) + d4);
            float4 xv2 = __ldcs(xw + 2 * (DIM / 4) + d4);
            float4 xv3 = __ldcs(xw + 3 * (DIM / 4) + d4);
            #pragma unroll
            for (int r = 0; r < RNK; r++) {
                float4 a = As4[r * 512 + d4];       // one read serves 4 rows
                acc[0][r] += dot4(xv0, a);
                acc[1][r] += dot4(xv1, a);
                acc[2][r] += dot4(xv2, a);
                acc[3][r] += dot4(xv3, a);
            }
        }
        #pragma unroll
        for (int jr = 0; jr < ROWS_PER_WARP; jr++) {
            #pragma unroll
            for (int r = 0; r < RNK; r++) {
                float s = acc[jr][r];
                #pragma unroll
                for (int off = 16; off; off >>= 1)
                    s += __shfl_xor_sync(0xffffffffu, s, off);
                if (lane == 0) xa2_s[warp * ROWS_PER_WARP + jr][r] = pack2(s);
            }
        }
    }
    __syncthreads();

    // ---- phase 2: thread owns 4 out cols; B built once; 64 rows, f32x2 ----
    {
        const float4* Bb4 = (const float4*)(g_B + b * RNK * DIM);
        ull Br0[RNK], Br1[RNK];
        #pragma unroll
        for (int r = 0; r < RNK; r++) {
            float4 bc = __ldg(Bb4 + r * (DIM / 4) + threadIdx.x);
            ulonglong2 p = *(ulonglong2*)&bc;
            Br0[r] = p.x;
            Br1[r] = p.y;
        }

        float4* orow = (float4*)(out + ((size_t)b * SEQ + row0) * DIM) + threadIdx.x;
        #pragma unroll 4
        for (int i = 0; i < ROWS_PER_BLOCK; i++) {
            ull o0 = 0ull, o1 = 0ull;
            #pragma unroll
            for (int r = 0; r < RNK; r++) {
                ull s2 = xa2_s[i][r];               // LDS.64 broadcast
                fma2(o0, s2, Br0[r]);
                fma2(o1, s2, Br1[r]);
            }
            ulonglong2 ov; ov.x = o0; ov.y = o1;
            __stcs(orow, *(float4*)&ov);
            orow += DIM / 4;
        }
    }
}

// ============================================================
// launcher
// ============================================================
extern "C" void kernel_launch(void* const* d_in, const int* in_sizes, int n_in,
                              void* d_out, int out_size) {
    const float* x     = (const float*)d_in[0];
    const float* ctr   = (const float*)d_in[1];
    const float* gamma = (const float*)d_in[2];
    const float* beta  = (const float*)d_in[3];
    const float* W1    = (const float*)d_in[4];
    const float* b1    = (const float*)d_in[5];
    const float* W2    = (const float*)d_in[6];
    const float* b2    = (const float*)d_in[7];
    const float* Wa    = (const float*)d_in[8];
    const float* Wb    = (const float*)d_in[9];
    float* out = (float*)d_out;

    static bool attr_set = false;
    if (!attr_set) {
        cudaFuncSetAttribute(main_kernel,
                             cudaFuncAttributeMaxDynamicSharedMemorySize,
                             RNK * DIM * (int)sizeof(float));
        attr_set = true;
    }

    gate_ab_kernel<<<(2 * RNK * DIM) / 512, 512>>>(ctr, gamma, beta,
                                                   W1, b1, W2, b2, Wa, Wb);
    main_kernel<<<BSZ * (SEQ / ROWS_PER_BLOCK), 512,
                  RNK * DIM * sizeof(float)>>>(x, out);
}